// round 1
// baseline (speedup 1.0000x reference)
#include <cuda_runtime.h>
#include <cuda_bf16.h>

// Problem constants
#define S_LEN 2048
#define HID   2048
#define NH    16
#define NKV   2
#define HD    128
#define SCALING 0.08838834764831845f

// Scratch (device globals: allocation-free rule)
__device__ float g_q[S_LEN * NH * HD];      // [s][h*128+d]  16MB
__device__ float g_k[S_LEN * NKV * HD];     // [s][kv*128+d]  2MB
__device__ float g_v[S_LEN * NKV * HD];     //                2MB
__device__ float g_attn[S_LEN * NH * HD];   // [s][h*128+d]  16MB

// ---------------------------------------------------------------------------
// SGEMM core: C[128,128] tile = A[M,K] @ B[K,N] (+bias), row-major, fp32.
// 256 threads, 8x8 per thread, BK=8. All dims multiples of tile sizes.
// ---------------------------------------------------------------------------
__device__ __forceinline__ void sgemm_body(
    const float* __restrict__ A, int lda,
    const float* __restrict__ B, int ldb,
    const float* __restrict__ bias,
    float* __restrict__ C, int ldc,
    int K, int m0, int n0)
{
    __shared__ float As[8][132];   // transposed A tile, padded
    __shared__ float Bs[8][128];

    const int tid  = threadIdx.x;
    const int arow = tid >> 1;          // 0..127
    const int ac4  = (tid & 1) * 4;     // 0 or 4
    const int brow = tid >> 5;          // 0..7
    const int bc4  = (tid & 31) * 4;    // 0..124
    const int tx   = tid & 15;
    const int ty   = tid >> 4;

    float acc[8][8];
#pragma unroll
    for (int i = 0; i < 8; i++)
#pragma unroll
        for (int j = 0; j < 8; j++) acc[i][j] = 0.0f;

    const float* Aptr = A + (size_t)(m0 + arow) * lda + ac4;
    const float* Bptr = B + (size_t)brow * ldb + n0 + bc4;

    for (int kk = 0; kk < K; kk += 8) {
        float4 av = *(const float4*)(Aptr + kk);
        float4 bv = *(const float4*)(Bptr + (size_t)kk * ldb);
        __syncthreads();
        As[ac4 + 0][arow] = av.x;
        As[ac4 + 1][arow] = av.y;
        As[ac4 + 2][arow] = av.z;
        As[ac4 + 3][arow] = av.w;
        *(float4*)&Bs[brow][bc4] = bv;
        __syncthreads();
#pragma unroll
        for (int k = 0; k < 8; k++) {
            float fa[8], fb[8];
            *(float4*)(fa)     = *(const float4*)&As[k][ty * 4];
            *(float4*)(fa + 4) = *(const float4*)&As[k][64 + ty * 4];
            *(float4*)(fb)     = *(const float4*)&Bs[k][tx * 4];
            *(float4*)(fb + 4) = *(const float4*)&Bs[k][64 + tx * 4];
#pragma unroll
            for (int i = 0; i < 8; i++)
#pragma unroll
                for (int j = 0; j < 8; j++)
                    acc[i][j] += fa[i] * fb[j];
        }
    }

    float bl[8];
#pragma unroll
    for (int u = 0; u < 4; u++) {
        bl[u]     = bias ? bias[n0 + tx * 4 + u]      : 0.0f;
        bl[u + 4] = bias ? bias[n0 + 64 + tx * 4 + u] : 0.0f;
    }

#pragma unroll
    for (int i = 0; i < 8; i++) {
        int r = m0 + ((i < 4) ? (ty * 4 + i) : (60 + ty * 4 + i));
        float4 v0, v1;
        v0.x = acc[i][0] + bl[0]; v0.y = acc[i][1] + bl[1];
        v0.z = acc[i][2] + bl[2]; v0.w = acc[i][3] + bl[3];
        v1.x = acc[i][4] + bl[4]; v1.y = acc[i][5] + bl[5];
        v1.z = acc[i][6] + bl[6]; v1.w = acc[i][7] + bl[7];
        *(float4*)&C[(size_t)r * ldc + n0 + tx * 4]      = v0;
        *(float4*)&C[(size_t)r * ldc + n0 + 64 + tx * 4] = v1;
    }
}

// Fused QKV projection: grid (20,16). bx<16 -> Q cols, 16..17 -> K, 18..19 -> V
__global__ void __launch_bounds__(256, 2) qkv_gemm_kernel(
    const float* __restrict__ hs,
    const float* __restrict__ Wq, const float* __restrict__ bq,
    const float* __restrict__ Wk, const float* __restrict__ bk,
    const float* __restrict__ Wv, const float* __restrict__ bv)
{
    int bx = blockIdx.x, by = blockIdx.y;
    const float* B; const float* bias; float* C; int ldn; int n0;
    if (bx < 16)      { B = Wq; bias = bq; C = g_q; ldn = NH * HD;  n0 = bx * 128; }
    else if (bx < 18) { B = Wk; bias = bk; C = g_k; ldn = NKV * HD; n0 = (bx - 16) * 128; }
    else              { B = Wv; bias = bv; C = g_v; ldn = NKV * HD; n0 = (bx - 18) * 128; }
    sgemm_body(hs, HID, B, ldn, bias, C, ldn, HID, by * 128, n0);
}

// O projection: grid (16,16)
__global__ void __launch_bounds__(256, 2) o_gemm_kernel(
    const float* __restrict__ Wo, float* __restrict__ out)
{
    sgemm_body(g_attn, NH * HD, Wo, HID, nullptr, out, HID,
               NH * HD, blockIdx.y * 128, blockIdx.x * 128);
}

// ---------------------------------------------------------------------------
// RoPE (in-place on g_q and g_k). One thread per (s, head, d<64) pair.
// cos/sin: [s][128] with cos[d] == cos[d+64].
// ---------------------------------------------------------------------------
__global__ void rope_kernel(const float* __restrict__ cosb,
                            const float* __restrict__ sinb)
{
    int idx = blockIdx.x * blockDim.x + threadIdx.x;
    const int QP = S_LEN * NH * 64;   // 2,097,152
    if (idx < QP) {
        int s = idx >> 10;            // /(16*64)
        int rest = idx & 1023;
        int h = rest >> 6;
        int d = rest & 63;
        float* p = g_q + (size_t)s * (NH * HD) + h * HD + d;
        float c  = cosb[s * HD + d];
        float sn = sinb[s * HD + d];
        float x0 = p[0], x1 = p[64];
        p[0]  = x0 * c - x1 * sn;
        p[64] = x1 * c + x0 * sn;
    } else {
        idx -= QP;                    // 262,144 K pairs
        int s = idx >> 7;             // /(2*64)
        int rest = idx & 127;
        int h = rest >> 6;
        int d = rest & 63;
        float* p = g_k + (size_t)s * (NKV * HD) + h * HD + d;
        float c  = cosb[s * HD + d];
        float sn = sinb[s * HD + d];
        float x0 = p[0], x1 = p[64];
        p[0]  = x0 * c - x1 * sn;
        p[64] = x1 * c + x0 * sn;
    }
}

// ---------------------------------------------------------------------------
// Flash attention, fp32. BM=BN=64, D=128, 256 threads.
// Thread t: row r = t>>2, col-group cg = t&3 (cols j*16+cg*4+u).
// grid (32, 16): (q-block, head). Causal: qb+1 tiles, mask diag tile.
// ---------------------------------------------------------------------------
#define FA_QS_OFF  0
#define FA_KT_OFF  8448          // 64*132
#define FA_VS_OFF  17152         // + 128*68
#define FA_SS_OFF  25344         // + 64*128
#define FA_SMEM_FLOATS 29696     // + 64*68
#define FA_SMEM_BYTES (FA_SMEM_FLOATS * 4)

__global__ void __launch_bounds__(256) flash_attn_kernel()
{
    extern __shared__ float sm[];
    float* Qs  = sm + FA_QS_OFF;   // [64][132]
    float* Kts = sm + FA_KT_OFF;   // [128][68]  (transposed K)
    float* Vs  = sm + FA_VS_OFF;   // [64][128]
    float* Ss  = sm + FA_SS_OFF;   // [64][68]

    const int tid  = threadIdx.x;
    const int head = blockIdx.y;
    const int kvh  = head >> 3;    // N_REP = 8
    const int r0   = blockIdx.x * 64;

    // Load Q tile (persistent)
#pragma unroll
    for (int f = 0; f < 8; f++) {
        int lin = f * 256 + tid;           // float4 index, 0..2047
        int row = lin >> 5;
        int c4  = (lin & 31) * 4;
        float4 v = *(const float4*)&g_q[(size_t)(r0 + row) * (NH * HD) + head * HD + c4];
        *(float4*)&Qs[row * 132 + c4] = v;
    }

    const int r  = tid >> 2;
    const int cg = tid & 3;

    float acc[32];
#pragma unroll
    for (int i = 0; i < 32; i++) acc[i] = 0.0f;
    float m = -1e30f, l = 0.0f;

    const int ntiles = blockIdx.x + 1;
    for (int t = 0; t < ntiles; t++) {
        const int k0 = t * 64;
        __syncthreads();   // prior-iter readers of Kts/Vs/Ss done
        // Load K (transposed) and V tiles
#pragma unroll
        for (int f = 0; f < 8; f++) {
            int lin = f * 256 + tid;
            int c  = lin >> 5;
            int d4 = (lin & 31) * 4;
            float4 kv = *(const float4*)&g_k[(size_t)(k0 + c) * (NKV * HD) + kvh * HD + d4];
            Kts[(d4 + 0) * 68 + c] = kv.x;
            Kts[(d4 + 1) * 68 + c] = kv.y;
            Kts[(d4 + 2) * 68 + c] = kv.z;
            Kts[(d4 + 3) * 68 + c] = kv.w;
            float4 vv = *(const float4*)&g_v[(size_t)(k0 + c) * (NKV * HD) + kvh * HD + d4];
            *(float4*)&Vs[c * 128 + d4] = vv;
        }
        __syncthreads();

        // S = Q @ K^T  (16 cols per thread, in registers)
        float s[16];
#pragma unroll
        for (int i = 0; i < 16; i++) s[i] = 0.0f;
#pragma unroll 4
        for (int d = 0; d < 128; d++) {
            float qv = Qs[r * 132 + d];
#pragma unroll
            for (int j = 0; j < 4; j++) {
                float4 kv = *(const float4*)&Kts[d * 68 + j * 16 + cg * 4];
                s[j * 4 + 0] += qv * kv.x;
                s[j * 4 + 1] += qv * kv.y;
                s[j * 4 + 2] += qv * kv.z;
                s[j * 4 + 3] += qv * kv.w;
            }
        }

        // Scale + causal mask + tile max
        const int diag_lim = r0 + r - k0;   // valid cols: c <= diag_lim
        float tmax = -1e30f;
#pragma unroll
        for (int j = 0; j < 4; j++)
#pragma unroll
            for (int u = 0; u < 4; u++) {
                int c = j * 16 + cg * 4 + u;
                float v = s[j * 4 + u] * SCALING;
                if (c > diag_lim) v = -1e30f;
                s[j * 4 + u] = v;
                tmax = fmaxf(tmax, v);
            }
        tmax = fmaxf(tmax, __shfl_xor_sync(0xffffffffu, tmax, 1));
        tmax = fmaxf(tmax, __shfl_xor_sync(0xffffffffu, tmax, 2));

        float mnew   = fmaxf(m, tmax);
        float factor = __expf(m - mnew);
        float tsum = 0.0f;
#pragma unroll
        for (int j = 0; j < 4; j++)
#pragma unroll
            for (int u = 0; u < 4; u++) {
                float p = __expf(s[j * 4 + u] - mnew);
                Ss[r * 68 + j * 16 + cg * 4 + u] = p;
                tsum += p;
            }
        tsum += __shfl_xor_sync(0xffffffffu, tsum, 1);
        tsum += __shfl_xor_sync(0xffffffffu, tsum, 2);
        l = l * factor + tsum;
        m = mnew;
#pragma unroll
        for (int i = 0; i < 32; i++) acc[i] *= factor;
        __syncthreads();   // Ss visible to all

        // acc += P @ V
#pragma unroll 4
        for (int kk = 0; kk < 64; kk++) {
            float p = Ss[r * 68 + kk];
#pragma unroll
            for (int j = 0; j < 8; j++) {
                float4 vv = *(const float4*)&Vs[kk * 128 + j * 16 + cg * 4];
                acc[j * 4 + 0] += p * vv.x;
                acc[j * 4 + 1] += p * vv.y;
                acc[j * 4 + 2] += p * vv.z;
                acc[j * 4 + 3] += p * vv.w;
            }
        }
    }

    float inv = 1.0f / l;
#pragma unroll
    for (int j = 0; j < 8; j++) {
        float4 o;
        o.x = acc[j * 4 + 0] * inv;
        o.y = acc[j * 4 + 1] * inv;
        o.z = acc[j * 4 + 2] * inv;
        o.w = acc[j * 4 + 3] * inv;
        *(float4*)&g_attn[(size_t)(r0 + r) * (NH * HD) + head * HD + j * 16 + cg * 4] = o;
    }
}

// ---------------------------------------------------------------------------
extern "C" void kernel_launch(void* const* d_in, const int* in_sizes, int n_in,
                              void* d_out, int out_size)
{
    const float* hs   = (const float*)d_in[0];
    const float* cosb = (const float*)d_in[1];
    const float* sinb = (const float*)d_in[2];
    // d_in[3] = attention_mask (pure causal; applied analytically)
    const float* Wq = (const float*)d_in[4];
    const float* bq = (const float*)d_in[5];
    const float* Wk = (const float*)d_in[6];
    const float* bk = (const float*)d_in[7];
    const float* Wv = (const float*)d_in[8];
    const float* bv = (const float*)d_in[9];
    const float* Wo = (const float*)d_in[10];
    float* out = (float*)d_out;

    cudaFuncSetAttribute(flash_attn_kernel,
                         cudaFuncAttributeMaxDynamicSharedMemorySize, FA_SMEM_BYTES);

    qkv_gemm_kernel<<<dim3(20, 16), 256>>>(hs, Wq, bq, Wk, bk, Wv, bv);
    rope_kernel<<<(S_LEN * NH * 64 + S_LEN * NKV * 64) / 256, 256>>>(cosb, sinb);
    flash_attn_kernel<<<dim3(32, 16), 256, FA_SMEM_BYTES>>>();
    o_gemm_kernel<<<dim3(16, 16), 256>>>(Wo, out);
}

// round 2
// speedup vs baseline: 1.4552x; 1.4552x over previous
#include <cuda_runtime.h>
#include <cuda_bf16.h>

// Problem constants
#define S_LEN 2048
#define HID   2048
#define NH    16
#define NKV   2
#define HD    128
#define SCALING 0.08838834764831845f

// Scratch (device globals: allocation-free rule)
__device__ float g_q[S_LEN * NH * HD];      // [s][h*128+d]  16MB
__device__ float g_k[S_LEN * NKV * HD];     // [s][kv*128+d]  2MB
__device__ float g_v[S_LEN * NKV * HD];     //                2MB
__device__ float g_attn[S_LEN * NH * HD];   // [s][h*128+d]  16MB

// ---------------------------------------------------------------------------
// SGEMM core: C[128,128] tile = A[M,K] @ B[K,N] (+bias), row-major, fp32.
// 256 threads, 8x8 per thread, BK=8.
// ---------------------------------------------------------------------------
__device__ __forceinline__ void sgemm_body(
    const float* __restrict__ A, int lda,
    const float* __restrict__ B, int ldb,
    const float* __restrict__ bias,
    float* __restrict__ C, int ldc,
    int K, int m0, int n0)
{
    __shared__ float As[8][132];   // transposed A tile, padded
    __shared__ float Bs[8][128];

    const int tid  = threadIdx.x;
    const int arow = tid >> 1;
    const int ac4  = (tid & 1) * 4;
    const int brow = tid >> 5;
    const int bc4  = (tid & 31) * 4;
    const int tx   = tid & 15;
    const int ty   = tid >> 4;

    float acc[8][8];
#pragma unroll
    for (int i = 0; i < 8; i++)
#pragma unroll
        for (int j = 0; j < 8; j++) acc[i][j] = 0.0f;

    const float* Aptr = A + (size_t)(m0 + arow) * lda + ac4;
    const float* Bptr = B + (size_t)brow * ldb + n0 + bc4;

    for (int kk = 0; kk < K; kk += 8) {
        float4 av = *(const float4*)(Aptr + kk);
        float4 bv = *(const float4*)(Bptr + (size_t)kk * ldb);
        __syncthreads();
        As[ac4 + 0][arow] = av.x;
        As[ac4 + 1][arow] = av.y;
        As[ac4 + 2][arow] = av.z;
        As[ac4 + 3][arow] = av.w;
        *(float4*)&Bs[brow][bc4] = bv;
        __syncthreads();
#pragma unroll
        for (int k = 0; k < 8; k++) {
            float fa[8], fb[8];
            *(float4*)(fa)     = *(const float4*)&As[k][ty * 4];
            *(float4*)(fa + 4) = *(const float4*)&As[k][64 + ty * 4];
            *(float4*)(fb)     = *(const float4*)&Bs[k][tx * 4];
            *(float4*)(fb + 4) = *(const float4*)&Bs[k][64 + tx * 4];
#pragma unroll
            for (int i = 0; i < 8; i++)
#pragma unroll
                for (int j = 0; j < 8; j++)
                    acc[i][j] += fa[i] * fb[j];
        }
    }

    float bl[8];
#pragma unroll
    for (int u = 0; u < 4; u++) {
        bl[u]     = bias ? bias[n0 + tx * 4 + u]      : 0.0f;
        bl[u + 4] = bias ? bias[n0 + 64 + tx * 4 + u] : 0.0f;
    }

#pragma unroll
    for (int i = 0; i < 8; i++) {
        int r = m0 + ((i < 4) ? (ty * 4 + i) : (60 + ty * 4 + i));
        float4 v0, v1;
        v0.x = acc[i][0] + bl[0]; v0.y = acc[i][1] + bl[1];
        v0.z = acc[i][2] + bl[2]; v0.w = acc[i][3] + bl[3];
        v1.x = acc[i][4] + bl[4]; v1.y = acc[i][5] + bl[5];
        v1.z = acc[i][6] + bl[6]; v1.w = acc[i][7] + bl[7];
        *(float4*)&C[(size_t)r * ldc + n0 + tx * 4]      = v0;
        *(float4*)&C[(size_t)r * ldc + n0 + 64 + tx * 4] = v1;
    }
}

__global__ void __launch_bounds__(256, 2) qkv_gemm_kernel(
    const float* __restrict__ hs,
    const float* __restrict__ Wq, const float* __restrict__ bq,
    const float* __restrict__ Wk, const float* __restrict__ bk,
    const float* __restrict__ Wv, const float* __restrict__ bv)
{
    int bx = blockIdx.x, by = blockIdx.y;
    const float* B; const float* bias; float* C; int ldn; int n0;
    if (bx < 16)      { B = Wq; bias = bq; C = g_q; ldn = NH * HD;  n0 = bx * 128; }
    else if (bx < 18) { B = Wk; bias = bk; C = g_k; ldn = NKV * HD; n0 = (bx - 16) * 128; }
    else              { B = Wv; bias = bv; C = g_v; ldn = NKV * HD; n0 = (bx - 18) * 128; }
    sgemm_body(hs, HID, B, ldn, bias, C, ldn, HID, by * 128, n0);
}

__global__ void __launch_bounds__(256, 2) o_gemm_kernel(
    const float* __restrict__ Wo, float* __restrict__ out)
{
    sgemm_body(g_attn, NH * HD, Wo, HID, nullptr, out, HID,
               NH * HD, blockIdx.y * 128, blockIdx.x * 128);
}

// ---------------------------------------------------------------------------
// RoPE (in-place on g_q and g_k).
// ---------------------------------------------------------------------------
__global__ void rope_kernel(const float* __restrict__ cosb,
                            const float* __restrict__ sinb)
{
    int idx = blockIdx.x * blockDim.x + threadIdx.x;
    const int QP = S_LEN * NH * 64;
    if (idx < QP) {
        int s = idx >> 10;
        int rest = idx & 1023;
        int h = rest >> 6;
        int d = rest & 63;
        float* p = g_q + (size_t)s * (NH * HD) + h * HD + d;
        float c  = cosb[s * HD + d];
        float sn = sinb[s * HD + d];
        float x0 = p[0], x1 = p[64];
        p[0]  = x0 * c - x1 * sn;
        p[64] = x1 * c + x0 * sn;
    } else {
        idx -= QP;
        int s = idx >> 7;
        int rest = idx & 127;
        int h = rest >> 6;
        int d = rest & 63;
        float* p = g_k + (size_t)s * (NKV * HD) + h * HD + d;
        float c  = cosb[s * HD + d];
        float sn = sinb[s * HD + d];
        float x0 = p[0], x1 = p[64];
        p[0]  = x0 * c - x1 * sn;
        p[64] = x1 * c + x0 * sn;
    }
}

// ---------------------------------------------------------------------------
// Flash attention, fp32, register-blocked like SGEMM.
// BM=128 (Q rows), BN=64 (K cols per tile), D=128. 256 threads as 16x16.
// Thread (tx,ty): S-fragment 8 rows x 4 cols; O-fragment 8 rows x 8 D-cols.
// Rows: m_i = ty*4+i (i<4), 64+ty*4+(i-4) (i>=4). S cols: tx*4+u.
// O cols: tx*4+j (j<4), 64+tx*4+(j-4).
// grid (16 qblocks, 16 heads); qb reversed for load balance. Causal: tiles
// 0..2qb+1, mask last two tiles.
// ---------------------------------------------------------------------------
#define FA2_QST_OFF 0                          // Qst[128][132] (transposed Q)
#define FA2_KS_OFF  (128 * 132)                // Ks[128][68]   (transposed K)
#define FA2_VS_OFF  (FA2_KS_OFF + 128 * 68)    // Vs[64][128]
#define FA2_PT_OFF  (FA2_VS_OFF + 64 * 128)    // Pt[64][132]   (transposed P)
#define FA2_SMEM_FLOATS (FA2_PT_OFF + 64 * 132)
#define FA2_SMEM_BYTES (FA2_SMEM_FLOATS * 4)   // 168,960 B

__global__ void __launch_bounds__(256, 1) flash_attn_kernel()
{
    extern __shared__ float sm[];
    float* Qst = sm + FA2_QST_OFF;
    float* Ks  = sm + FA2_KS_OFF;
    float* Vs  = sm + FA2_VS_OFF;
    float* Pt  = sm + FA2_PT_OFF;

    const int tid  = threadIdx.x;
    const int head = blockIdx.y;
    const int kvh  = head >> 3;           // N_REP = 8
    const int qb   = 15 - blockIdx.x;     // big blocks first
    const int r0   = qb * 128;
    const int tx   = tid & 15;
    const int ty   = tid >> 4;

    // Load Q tile transposed: Qst[d][row]
#pragma unroll
    for (int f = 0; f < 8; f++) {
        int lin = f * 256 + tid;              // float4 idx 0..2047
        int row = lin >> 5;                   // 0..63? no: 2048/32 = 64.. need rows 0..127
        int c4  = (lin & 31) * 4;
        // 128 rows x 32 float4/row = 4096 float4 -> need 16 iters of 256
        (void)row; (void)c4;
    }
    // (redo properly: 4096 float4 total)
#pragma unroll
    for (int f = 0; f < 16; f++) {
        int lin = f * 256 + tid;              // 0..4095
        int row = lin >> 5;                   // 0..127
        int c4  = (lin & 31) * 4;             // 0..124
        float4 v = *(const float4*)&g_q[(size_t)(r0 + row) * (NH * HD) + head * HD + c4];
        Qst[(c4 + 0) * 132 + row] = v.x;
        Qst[(c4 + 1) * 132 + row] = v.y;
        Qst[(c4 + 2) * 132 + row] = v.z;
        Qst[(c4 + 3) * 132 + row] = v.w;
    }

    float acc[8][8];
#pragma unroll
    for (int i = 0; i < 8; i++)
#pragma unroll
        for (int j = 0; j < 8; j++) acc[i][j] = 0.0f;
    float mrow[8], lrow[8];
#pragma unroll
    for (int i = 0; i < 8; i++) { mrow[i] = -1e30f; lrow[i] = 0.0f; }

    int m_g[8];   // global row per fragment row
#pragma unroll
    for (int i = 0; i < 8; i++)
        m_g[i] = r0 + ((i < 4) ? (ty * 4 + i) : (60 + ty * 4 + i));

    const int ntiles = 2 * qb + 2;
    for (int t = 0; t < ntiles; t++) {
        const int k0 = t * 64;
        __syncthreads();   // prior-iter readers of Ks/Vs done; Qst writes done (t=0)

        // Load K transposed (Ks[d][c]) and V (Vs[c][d]); 64 rows x 32 float4 = 2048
#pragma unroll
        for (int f = 0; f < 8; f++) {
            int lin = f * 256 + tid;
            int c  = lin >> 5;                // 0..63
            int d4 = (lin & 31) * 4;
            float4 kv = *(const float4*)&g_k[(size_t)(k0 + c) * (NKV * HD) + kvh * HD + d4];
            Ks[(d4 + 0) * 68 + c] = kv.x;
            Ks[(d4 + 1) * 68 + c] = kv.y;
            Ks[(d4 + 2) * 68 + c] = kv.z;
            Ks[(d4 + 3) * 68 + c] = kv.w;
            float4 vv = *(const float4*)&g_v[(size_t)(k0 + c) * (NKV * HD) + kvh * HD + d4];
            *(float4*)&Vs[c * 128 + d4] = vv;
        }
        __syncthreads();

        // ---- S = Q @ K^T (register tile 8x4 per thread) ----
        float s[8][4];
#pragma unroll
        for (int i = 0; i < 8; i++)
#pragma unroll
            for (int u = 0; u < 4; u++) s[i][u] = 0.0f;

#pragma unroll 4
        for (int d = 0; d < 128; d++) {
            float fa[8], fb[4];
            *(float4*)(fa)     = *(const float4*)&Qst[d * 132 + ty * 4];
            *(float4*)(fa + 4) = *(const float4*)&Qst[d * 132 + 64 + ty * 4];
            *(float4*)(fb)     = *(const float4*)&Ks[d * 68 + tx * 4];
#pragma unroll
            for (int i = 0; i < 8; i++)
#pragma unroll
                for (int u = 0; u < 4; u++)
                    s[i][u] += fa[i] * fb[u];
        }

        // ---- scale + causal mask + online softmax ----
        const bool need_mask = (t >= ntiles - 2);
#pragma unroll
        for (int i = 0; i < 8; i++) {
            float tmax = -1e30f;
#pragma unroll
            for (int u = 0; u < 4; u++) {
                float v = s[i][u] * SCALING;
                if (need_mask) {
                    int cglob = k0 + tx * 4 + u;
                    if (cglob > m_g[i]) v = -1e30f;
                }
                s[i][u] = v;
                tmax = fmaxf(tmax, v);
            }
            // reduce max over 16 tx lanes (contiguous within half-warp)
            tmax = fmaxf(tmax, __shfl_xor_sync(0xffffffffu, tmax, 1));
            tmax = fmaxf(tmax, __shfl_xor_sync(0xffffffffu, tmax, 2));
            tmax = fmaxf(tmax, __shfl_xor_sync(0xffffffffu, tmax, 4));
            tmax = fmaxf(tmax, __shfl_xor_sync(0xffffffffu, tmax, 8));

            float mnew   = fmaxf(mrow[i], tmax);
            float factor = __expf(mrow[i] - mnew);
            float tsum = 0.0f;
#pragma unroll
            for (int u = 0; u < 4; u++) {
                float p = __expf(s[i][u] - mnew);
                s[i][u] = p;
                tsum += p;
            }
            tsum += __shfl_xor_sync(0xffffffffu, tsum, 1);
            tsum += __shfl_xor_sync(0xffffffffu, tsum, 2);
            tsum += __shfl_xor_sync(0xffffffffu, tsum, 4);
            tsum += __shfl_xor_sync(0xffffffffu, tsum, 8);

            lrow[i] = lrow[i] * factor + tsum;
            mrow[i] = mnew;
#pragma unroll
            for (int j = 0; j < 8; j++) acc[i][j] *= factor;
        }

        // store P transposed: Pt[c][row]
#pragma unroll
        for (int i = 0; i < 8; i++) {
            int mloc = m_g[i] - r0;
#pragma unroll
            for (int u = 0; u < 4; u++)
                Pt[(tx * 4 + u) * 132 + mloc] = s[i][u];
        }
        __syncthreads();

        // ---- acc += P @ V ----
#pragma unroll 4
        for (int k = 0; k < 64; k++) {
            float fa2[8], fb2[8];
            *(float4*)(fa2)     = *(const float4*)&Pt[k * 132 + ty * 4];
            *(float4*)(fa2 + 4) = *(const float4*)&Pt[k * 132 + 64 + ty * 4];
            *(float4*)(fb2)     = *(const float4*)&Vs[k * 128 + tx * 4];
            *(float4*)(fb2 + 4) = *(const float4*)&Vs[k * 128 + 64 + tx * 4];
#pragma unroll
            for (int i = 0; i < 8; i++)
#pragma unroll
                for (int j = 0; j < 8; j++)
                    acc[i][j] += fa2[i] * fb2[j];
        }
    }

    // epilogue: normalize and write O
#pragma unroll
    for (int i = 0; i < 8; i++) {
        float inv = 1.0f / lrow[i];
        float4 v0, v1;
        v0.x = acc[i][0] * inv; v0.y = acc[i][1] * inv;
        v0.z = acc[i][2] * inv; v0.w = acc[i][3] * inv;
        v1.x = acc[i][4] * inv; v1.y = acc[i][5] * inv;
        v1.z = acc[i][6] * inv; v1.w = acc[i][7] * inv;
        float* dst = &g_attn[(size_t)m_g[i] * (NH * HD) + head * HD];
        *(float4*)&dst[tx * 4]      = v0;
        *(float4*)&dst[64 + tx * 4] = v1;
    }
}

// ---------------------------------------------------------------------------
extern "C" void kernel_launch(void* const* d_in, const int* in_sizes, int n_in,
                              void* d_out, int out_size)
{
    const float* hs   = (const float*)d_in[0];
    const float* cosb = (const float*)d_in[1];
    const float* sinb = (const float*)d_in[2];
    // d_in[3] = attention_mask (pure causal; applied analytically)
    const float* Wq = (const float*)d_in[4];
    const float* bq = (const float*)d_in[5];
    const float* Wk = (const float*)d_in[6];
    const float* bk = (const float*)d_in[7];
    const float* Wv = (const float*)d_in[8];
    const float* bv = (const float*)d_in[9];
    const float* Wo = (const float*)d_in[10];
    float* out = (float*)d_out;

    cudaFuncSetAttribute(flash_attn_kernel,
                         cudaFuncAttributeMaxDynamicSharedMemorySize, FA2_SMEM_BYTES);

    qkv_gemm_kernel<<<dim3(20, 16), 256>>>(hs, Wq, bq, Wk, bk, Wv, bv);
    rope_kernel<<<(S_LEN * NH * 64 + S_LEN * NKV * 64) / 256, 256>>>(cosb, sinb);
    flash_attn_kernel<<<dim3(16, 16), 256, FA2_SMEM_BYTES>>>();
    o_gemm_kernel<<<dim3(16, 16), 256>>>(Wo, out);
}

// round 3
// speedup vs baseline: 3.0184x; 2.0742x over previous
#include <cuda_runtime.h>
#include <cuda_bf16.h>

// Problem constants
#define S_LEN 2048
#define HID   2048
#define NH    16
#define NKV   2
#define HD    128
#define SCALING 0.08838834764831845f

// Scratch (device globals: allocation-free rule)
__device__ float g_q[S_LEN * NH * HD];      // [s][h*128+d]
__device__ float g_k[S_LEN * NKV * HD];     // [s][kv*128+d]
__device__ float g_v[S_LEN * NKV * HD];
__device__ float g_attn[S_LEN * NH * HD];

// ---------------------------------------------------------------------------
// TF32 helpers
// ---------------------------------------------------------------------------
__device__ __forceinline__ float tf32r(float f) {
    unsigned u;
    asm("cvt.rna.tf32.f32 %0, %1;" : "=r"(u) : "f"(f));
    return __uint_as_float(u);
}

// mma.m16n8k8 tf32, fp32 accumulate. Layout (lane = 4*qt+qr, qt=lane/4, qr=lane%4):
//  A(16x8) row-major: a0=A[qt][qr] a1=A[qt+8][qr] a2=A[qt][qr+4] a3=A[qt+8][qr+4]
//  B(8x8)  col-major: b0=B[qr][qt] b1=B[qr+4][qt]
//  C(16x8): c0=C[qt][2qr] c1=C[qt][2qr+1] c2=C[qt+8][2qr] c3=C[qt+8][2qr+1]
__device__ __forceinline__ void mma8(float* c,
    unsigned a0, unsigned a1, unsigned a2, unsigned a3,
    unsigned b0, unsigned b1)
{
    asm volatile(
        "mma.sync.aligned.m16n8k8.row.col.f32.tf32.tf32.f32 "
        "{%0,%1,%2,%3}, {%4,%5,%6,%7}, {%8,%9}, {%0,%1,%2,%3};\n"
        : "+f"(c[0]), "+f"(c[1]), "+f"(c[2]), "+f"(c[3])
        : "r"(a0), "r"(a1), "r"(a2), "r"(a3), "r"(b0), "r"(b1));
}

// ---------------------------------------------------------------------------
// TF32 GEMM: C[128,128] tile = A[M,K] @ B[K,N] (+bias). 256 threads, 8 warps.
// Warp tile 32x64 (warp_m = wid&3, warp_n = wid>>2). BK=32.
// As[128][36] (row-major, pad 4), Bs[32][136] (row-major, pad 8).
// ---------------------------------------------------------------------------
#define G_LDA 36
#define G_LDB 136

__device__ __forceinline__ void gemm_tf32(
    const float* __restrict__ A, int lda,
    const float* __restrict__ B, int ldb,
    const float* __restrict__ bias,
    float* __restrict__ C, int ldc,
    int K, int m0, int n0)
{
    __shared__ float As[128 * G_LDA];
    __shared__ float Bs[32 * G_LDB];

    const int tid  = threadIdx.x;
    const int wid  = tid >> 5;
    const int lane = tid & 31;
    const int qt   = lane >> 2;          // 0..7
    const int qr   = lane & 3;           // 0..3
    const int wm   = (wid & 3) * 32;
    const int wn   = (wid >> 2) * 64;

    float c[2][8][4];
#pragma unroll
    for (int mf = 0; mf < 2; mf++)
#pragma unroll
        for (int nf = 0; nf < 8; nf++)
#pragma unroll
            for (int e = 0; e < 4; e++) c[mf][nf][e] = 0.0f;

    for (int kk = 0; kk < K; kk += 32) {
        __syncthreads();
        // Load A tile 128x32 (1024 float4, 4/thread)
#pragma unroll
        for (int f = 0; f < 4; f++) {
            int lin = f * 256 + tid;
            int row = lin >> 3;
            int c4  = (lin & 7) * 4;
            float4 v = *(const float4*)&A[(size_t)(m0 + row) * lda + kk + c4];
            As[row * G_LDA + c4 + 0] = tf32r(v.x);
            As[row * G_LDA + c4 + 1] = tf32r(v.y);
            As[row * G_LDA + c4 + 2] = tf32r(v.z);
            As[row * G_LDA + c4 + 3] = tf32r(v.w);
        }
        // Load B tile 32x128
#pragma unroll
        for (int f = 0; f < 4; f++) {
            int lin = f * 256 + tid;
            int row = lin >> 5;
            int c4  = (lin & 31) * 4;
            float4 v = *(const float4*)&B[(size_t)(kk + row) * ldb + n0 + c4];
            Bs[row * G_LDB + c4 + 0] = tf32r(v.x);
            Bs[row * G_LDB + c4 + 1] = tf32r(v.y);
            Bs[row * G_LDB + c4 + 2] = tf32r(v.z);
            Bs[row * G_LDB + c4 + 3] = tf32r(v.w);
        }
        __syncthreads();

#pragma unroll
        for (int ks = 0; ks < 32; ks += 8) {
            unsigned a[2][4];
#pragma unroll
            for (int mf = 0; mf < 2; mf++) {
                int r = wm + mf * 16 + qt;
                a[mf][0] = __float_as_uint(As[r * G_LDA + ks + qr]);
                a[mf][1] = __float_as_uint(As[(r + 8) * G_LDA + ks + qr]);
                a[mf][2] = __float_as_uint(As[r * G_LDA + ks + qr + 4]);
                a[mf][3] = __float_as_uint(As[(r + 8) * G_LDA + ks + qr + 4]);
            }
#pragma unroll
            for (int nf = 0; nf < 8; nf++) {
                unsigned b0 = __float_as_uint(Bs[(ks + qr) * G_LDB + wn + nf * 8 + qt]);
                unsigned b1 = __float_as_uint(Bs[(ks + qr + 4) * G_LDB + wn + nf * 8 + qt]);
                mma8(c[0][nf], a[0][0], a[0][1], a[0][2], a[0][3], b0, b1);
                mma8(c[1][nf], a[1][0], a[1][1], a[1][2], a[1][3], b0, b1);
            }
        }
    }

    // Epilogue: direct global writes (known accumulator layout), bias in regs
#pragma unroll
    for (int nf = 0; nf < 8; nf++) {
        int col = n0 + wn + nf * 8 + 2 * qr;
        float b0 = bias ? bias[col]     : 0.0f;
        float b1 = bias ? bias[col + 1] : 0.0f;
#pragma unroll
        for (int mf = 0; mf < 2; mf++) {
            int r = m0 + wm + mf * 16 + qt;
            float2 v0, v1;
            v0.x = c[mf][nf][0] + b0; v0.y = c[mf][nf][1] + b1;
            v1.x = c[mf][nf][2] + b0; v1.y = c[mf][nf][3] + b1;
            *(float2*)&C[(size_t)r * ldc + col]       = v0;
            *(float2*)&C[(size_t)(r + 8) * ldc + col] = v1;
        }
    }
}

__global__ void __launch_bounds__(256, 2) qkv_gemm_kernel(
    const float* __restrict__ hs,
    const float* __restrict__ Wq, const float* __restrict__ bq,
    const float* __restrict__ Wk, const float* __restrict__ bk,
    const float* __restrict__ Wv, const float* __restrict__ bv)
{
    int bx = blockIdx.x, by = blockIdx.y;
    const float* B; const float* bias; float* C; int ldn; int n0;
    if (bx < 16)      { B = Wq; bias = bq; C = g_q; ldn = NH * HD;  n0 = bx * 128; }
    else if (bx < 18) { B = Wk; bias = bk; C = g_k; ldn = NKV * HD; n0 = (bx - 16) * 128; }
    else              { B = Wv; bias = bv; C = g_v; ldn = NKV * HD; n0 = (bx - 18) * 128; }
    gemm_tf32(hs, HID, B, ldn, bias, C, ldn, HID, by * 128, n0);
}

__global__ void __launch_bounds__(256, 2) o_gemm_kernel(
    const float* __restrict__ Wo, float* __restrict__ out)
{
    gemm_tf32(g_attn, NH * HD, Wo, HID, nullptr, out, HID,
              NH * HD, blockIdx.y * 128, blockIdx.x * 128);
}

// ---------------------------------------------------------------------------
// RoPE (in-place on g_q and g_k), fp32.
// ---------------------------------------------------------------------------
__global__ void rope_kernel(const float* __restrict__ cosb,
                            const float* __restrict__ sinb)
{
    int idx = blockIdx.x * blockDim.x + threadIdx.x;
    const int QP = S_LEN * NH * 64;
    if (idx < QP) {
        int s = idx >> 10;
        int rest = idx & 1023;
        int h = rest >> 6;
        int d = rest & 63;
        float* p = g_q + (size_t)s * (NH * HD) + h * HD + d;
        float c  = cosb[s * HD + d];
        float sn = sinb[s * HD + d];
        float x0 = p[0], x1 = p[64];
        p[0]  = x0 * c - x1 * sn;
        p[64] = x1 * c + x0 * sn;
    } else {
        idx -= QP;
        int s = idx >> 7;
        int rest = idx & 127;
        int h = rest >> 6;
        int d = rest & 63;
        float* p = g_k + (size_t)s * (NKV * HD) + h * HD + d;
        float c  = cosb[s * HD + d];
        float sn = sinb[s * HD + d];
        float x0 = p[0], x1 = p[64];
        p[0]  = x0 * c - x1 * sn;
        p[64] = x1 * c + x0 * sn;
    }
}

// ---------------------------------------------------------------------------
// Flash attention, tf32 tensor cores.
// BM=128 Q rows, BN=64 K cols/tile, D=128. 256 threads, 8 warps.
// Warp wid owns S rows [wid*16, wid*16+16) x all 64 cols -> softmax rows are
// warp-local (reduce over 4 lanes). O accum: 16 n-frags (128 d-cols) in regs.
// P staged through smem but only read by the warp that wrote it (__syncwarp).
// Q pre-scaled by SCALING. Causal: tiles 0..2qb+1, mask last two.
// ---------------------------------------------------------------------------
#define AT_LDQ 132
#define AT_LDK 132
#define AT_LDV 136
#define AT_LDP 68
#define AT_QS  0
#define AT_KS  (128 * AT_LDQ)
#define AT_VS  (AT_KS + 64 * AT_LDK)
#define AT_PS  (AT_VS + 64 * AT_LDV)
#define AT_FLOATS (AT_PS + 128 * AT_LDP)
#define AT_SMEM_BYTES (AT_FLOATS * 4)    // 171,008 B

__global__ void __launch_bounds__(256, 1) flash_attn_kernel()
{
    extern __shared__ float sm[];
    float* Qs = sm + AT_QS;
    float* Ks = sm + AT_KS;
    float* Vs = sm + AT_VS;
    float* Ps = sm + AT_PS;

    const int tid  = threadIdx.x;
    const int wid  = tid >> 5;
    const int lane = tid & 31;
    const int qt   = lane >> 2;
    const int qr   = lane & 3;
    const int head = blockIdx.y;
    const int kvh  = head >> 3;           // N_REP = 8
    const int qb   = 15 - blockIdx.x;     // big blocks first
    const int r0   = qb * 128;

    // Load Q tile (scaled, tf32-rounded): 128x128 = 4096 float4
#pragma unroll
    for (int f = 0; f < 16; f++) {
        int lin = f * 256 + tid;
        int row = lin >> 5;
        int c4  = (lin & 31) * 4;
        float4 v = *(const float4*)&g_q[(size_t)(r0 + row) * (NH * HD) + head * HD + c4];
        Qs[row * AT_LDQ + c4 + 0] = tf32r(v.x * SCALING);
        Qs[row * AT_LDQ + c4 + 1] = tf32r(v.y * SCALING);
        Qs[row * AT_LDQ + c4 + 2] = tf32r(v.z * SCALING);
        Qs[row * AT_LDQ + c4 + 3] = tf32r(v.w * SCALING);
    }

    const int row_lo = wid * 16 + qt;     // local S/O row (lo)
    const int row_hi = row_lo + 8;

    float o[16][4];
#pragma unroll
    for (int nf = 0; nf < 16; nf++)
#pragma unroll
        for (int e = 0; e < 4; e++) o[nf][e] = 0.0f;
    float m_lo = -1e30f, m_hi = -1e30f, l_lo = 0.0f, l_hi = 0.0f;

    const int ntiles = 2 * qb + 2;
    for (int t = 0; t < ntiles; t++) {
        const int k0 = t * 64;
        __syncthreads();   // all warps done reading prior Ks/Vs (and Qs stores at t=0)

        // Load K/V tiles (tf32-rounded): each 64x128 = 2048 float4, 8/thread
#pragma unroll
        for (int f = 0; f < 8; f++) {
            int lin = f * 256 + tid;
            int cc = lin >> 5;
            int d4 = (lin & 31) * 4;
            float4 kv = *(const float4*)&g_k[(size_t)(k0 + cc) * (NKV * HD) + kvh * HD + d4];
            Ks[cc * AT_LDK + d4 + 0] = tf32r(kv.x);
            Ks[cc * AT_LDK + d4 + 1] = tf32r(kv.y);
            Ks[cc * AT_LDK + d4 + 2] = tf32r(kv.z);
            Ks[cc * AT_LDK + d4 + 3] = tf32r(kv.w);
            float4 vv = *(const float4*)&g_v[(size_t)(k0 + cc) * (NKV * HD) + kvh * HD + d4];
            Vs[cc * AT_LDV + d4 + 0] = tf32r(vv.x);
            Vs[cc * AT_LDV + d4 + 1] = tf32r(vv.y);
            Vs[cc * AT_LDV + d4 + 2] = tf32r(vv.z);
            Vs[cc * AT_LDV + d4 + 3] = tf32r(vv.w);
        }
        __syncthreads();

        // ---- S = Q @ K^T : s[8][4] (16 rows x 64 cols per warp) ----
        float s[8][4];
#pragma unroll
        for (int nf = 0; nf < 8; nf++)
#pragma unroll
            for (int e = 0; e < 4; e++) s[nf][e] = 0.0f;

#pragma unroll
        for (int ks = 0; ks < 128; ks += 8) {
            unsigned a0 = __float_as_uint(Qs[row_lo * AT_LDQ + ks + qr]);
            unsigned a1 = __float_as_uint(Qs[row_hi * AT_LDQ + ks + qr]);
            unsigned a2 = __float_as_uint(Qs[row_lo * AT_LDQ + ks + qr + 4]);
            unsigned a3 = __float_as_uint(Qs[row_hi * AT_LDQ + ks + qr + 4]);
#pragma unroll
            for (int nf = 0; nf < 8; nf++) {
                unsigned b0 = __float_as_uint(Ks[(nf * 8 + qt) * AT_LDK + ks + qr]);
                unsigned b1 = __float_as_uint(Ks[(nf * 8 + qt) * AT_LDK + ks + qr + 4]);
                mma8(s[nf], a0, a1, a2, a3, b0, b1);
            }
        }

        // ---- causal mask + online softmax (rows warp-local) ----
        const bool need_mask = (t >= ntiles - 2);
        float mx_lo = -1e30f, mx_hi = -1e30f;
#pragma unroll
        for (int nf = 0; nf < 8; nf++) {
            if (need_mask) {
                int cg = k0 + nf * 8 + 2 * qr;
                int rg_lo = r0 + row_lo, rg_hi = r0 + row_hi;
                if (cg     > rg_lo) s[nf][0] = -1e30f;
                if (cg + 1 > rg_lo) s[nf][1] = -1e30f;
                if (cg     > rg_hi) s[nf][2] = -1e30f;
                if (cg + 1 > rg_hi) s[nf][3] = -1e30f;
            }
            mx_lo = fmaxf(mx_lo, fmaxf(s[nf][0], s[nf][1]));
            mx_hi = fmaxf(mx_hi, fmaxf(s[nf][2], s[nf][3]));
        }
        mx_lo = fmaxf(mx_lo, __shfl_xor_sync(0xffffffffu, mx_lo, 1));
        mx_lo = fmaxf(mx_lo, __shfl_xor_sync(0xffffffffu, mx_lo, 2));
        mx_hi = fmaxf(mx_hi, __shfl_xor_sync(0xffffffffu, mx_hi, 1));
        mx_hi = fmaxf(mx_hi, __shfl_xor_sync(0xffffffffu, mx_hi, 2));

        float mn_lo = fmaxf(m_lo, mx_lo);
        float mn_hi = fmaxf(m_hi, mx_hi);
        float f_lo = __expf(m_lo - mn_lo);
        float f_hi = __expf(m_hi - mn_hi);
        float sum_lo = 0.0f, sum_hi = 0.0f;
#pragma unroll
        for (int nf = 0; nf < 8; nf++) {
            float p0 = __expf(s[nf][0] - mn_lo);
            float p1 = __expf(s[nf][1] - mn_lo);
            float p2 = __expf(s[nf][2] - mn_hi);
            float p3 = __expf(s[nf][3] - mn_hi);
            sum_lo += p0 + p1;
            sum_hi += p2 + p3;
            int col = nf * 8 + 2 * qr;
            Ps[row_lo * AT_LDP + col]     = tf32r(p0);
            Ps[row_lo * AT_LDP + col + 1] = tf32r(p1);
            Ps[row_hi * AT_LDP + col]     = tf32r(p2);
            Ps[row_hi * AT_LDP + col + 1] = tf32r(p3);
        }
        sum_lo += __shfl_xor_sync(0xffffffffu, sum_lo, 1);
        sum_lo += __shfl_xor_sync(0xffffffffu, sum_lo, 2);
        sum_hi += __shfl_xor_sync(0xffffffffu, sum_hi, 1);
        sum_hi += __shfl_xor_sync(0xffffffffu, sum_hi, 2);

        l_lo = l_lo * f_lo + sum_lo;
        l_hi = l_hi * f_hi + sum_hi;
        m_lo = mn_lo;
        m_hi = mn_hi;
#pragma unroll
        for (int nf = 0; nf < 16; nf++) {
            o[nf][0] *= f_lo; o[nf][1] *= f_lo;
            o[nf][2] *= f_hi; o[nf][3] *= f_hi;
        }
        __syncwarp();   // Ps rows of this warp written by this warp only

        // ---- O += P @ V : 8 k-steps over 64 tokens ----
#pragma unroll
        for (int ks = 0; ks < 64; ks += 8) {
            unsigned a0 = __float_as_uint(Ps[row_lo * AT_LDP + ks + qr]);
            unsigned a1 = __float_as_uint(Ps[row_hi * AT_LDP + ks + qr]);
            unsigned a2 = __float_as_uint(Ps[row_lo * AT_LDP + ks + qr + 4]);
            unsigned a3 = __float_as_uint(Ps[row_hi * AT_LDP + ks + qr + 4]);
#pragma unroll
            for (int nf = 0; nf < 16; nf++) {
                unsigned b0 = __float_as_uint(Vs[(ks + qr) * AT_LDV + nf * 8 + qt]);
                unsigned b1 = __float_as_uint(Vs[(ks + qr + 4) * AT_LDV + nf * 8 + qt]);
                mma8(o[nf], a0, a1, a2, a3, b0, b1);
            }
        }
        __syncwarp();   // done reading Ps before next-iter overwrite
    }

    // Epilogue: normalize, write O
    float inv_lo = 1.0f / l_lo;
    float inv_hi = 1.0f / l_hi;
#pragma unroll
    for (int nf = 0; nf < 16; nf++) {
        int col = head * HD + nf * 8 + 2 * qr;
        float2 v0, v1;
        v0.x = o[nf][0] * inv_lo; v0.y = o[nf][1] * inv_lo;
        v1.x = o[nf][2] * inv_hi; v1.y = o[nf][3] * inv_hi;
        *(float2*)&g_attn[(size_t)(r0 + row_lo) * (NH * HD) + col] = v0;
        *(float2*)&g_attn[(size_t)(r0 + row_hi) * (NH * HD) + col] = v1;
    }
}

// ---------------------------------------------------------------------------
extern "C" void kernel_launch(void* const* d_in, const int* in_sizes, int n_in,
                              void* d_out, int out_size)
{
    const float* hs   = (const float*)d_in[0];
    const float* cosb = (const float*)d_in[1];
    const float* sinb = (const float*)d_in[2];
    // d_in[3] = attention_mask (pure causal; applied analytically)
    const float* Wq = (const float*)d_in[4];
    const float* bq = (const float*)d_in[5];
    const float* Wk = (const float*)d_in[6];
    const float* bk = (const float*)d_in[7];
    const float* Wv = (const float*)d_in[8];
    const float* bv = (const float*)d_in[9];
    const float* Wo = (const float*)d_in[10];
    float* out = (float*)d_out;

    cudaFuncSetAttribute(flash_attn_kernel,
                         cudaFuncAttributeMaxDynamicSharedMemorySize, AT_SMEM_BYTES);

    qkv_gemm_kernel<<<dim3(20, 16), 256>>>(hs, Wq, bq, Wk, bk, Wv, bv);
    rope_kernel<<<(S_LEN * NH * 64 + S_LEN * NKV * 64) / 256, 256>>>(cosb, sinb);
    flash_attn_kernel<<<dim3(16, 16), 256, AT_SMEM_BYTES>>>();
    o_gemm_kernel<<<dim3(16, 16), 256>>>(Wo, out);
}

// round 4
// speedup vs baseline: 3.3035x; 1.0945x over previous
#include <cuda_runtime.h>
#include <cuda_bf16.h>

// Problem constants
#define S_LEN 2048
#define HID   2048
#define NH    16
#define NKV   2
#define HD    128
#define SCALING 0.08838834764831845f

// Scratch (device globals: allocation-free rule)
__device__ float g_q[S_LEN * NH * HD];
__device__ float g_k[S_LEN * NKV * HD];
__device__ float g_v[S_LEN * NKV * HD];
__device__ float g_attn[S_LEN * NH * HD];
// tf32-prerounded copies of inputs
__device__ float g_hs[S_LEN * HID];
__device__ float g_wq[HID * NH * HD];
__device__ float g_wk[HID * NKV * HD];
__device__ float g_wv[HID * NKV * HD];
__device__ float g_wo[NH * HD * HID];

// ---------------------------------------------------------------------------
// TF32 + cp.async helpers
// ---------------------------------------------------------------------------
__device__ __forceinline__ float tf32r(float f) {
    unsigned u;
    asm("cvt.rna.tf32.f32 %0, %1;" : "=r"(u) : "f"(f));
    return __uint_as_float(u);
}

__device__ __forceinline__ void mma8(float* c,
    unsigned a0, unsigned a1, unsigned a2, unsigned a3,
    unsigned b0, unsigned b1)
{
    asm volatile(
        "mma.sync.aligned.m16n8k8.row.col.f32.tf32.tf32.f32 "
        "{%0,%1,%2,%3}, {%4,%5,%6,%7}, {%8,%9}, {%0,%1,%2,%3};\n"
        : "+f"(c[0]), "+f"(c[1]), "+f"(c[2]), "+f"(c[3])
        : "r"(a0), "r"(a1), "r"(a2), "r"(a3), "r"(b0), "r"(b1));
}

__device__ __forceinline__ void cp16(unsigned saddr, const void* gptr) {
    asm volatile("cp.async.cg.shared.global [%0], [%1], 16;\n"
                 :: "r"(saddr), "l"(gptr));
}
__device__ __forceinline__ void cp_commit() {
    asm volatile("cp.async.commit_group;\n");
}
template<int N>
__device__ __forceinline__ void cp_wait() {
    asm volatile("cp.async.wait_group %0;\n" :: "n"(N));
}

// ---------------------------------------------------------------------------
// Prepass: round hs + weights to tf32 once.
// ---------------------------------------------------------------------------
#define HS4  1048576
#define WQ4  1048576
#define WK4  131072
#define WV4  131072
#define WO4  1048576
#define TOT4 (HS4 + WQ4 + WK4 + WV4 + WO4)    // 3,407,872

__global__ void tf32_prepass_kernel(
    const float4* __restrict__ hs, const float4* __restrict__ wq,
    const float4* __restrict__ wk, const float4* __restrict__ wv,
    const float4* __restrict__ wo)
{
    int i = blockIdx.x * 256 + threadIdx.x;
    if (i >= TOT4) return;
    const float4* s; float4* d; int o;
    if (i < HS4)                         { s = hs; d = (float4*)g_hs; o = i; }
    else if (i < HS4 + WQ4)              { s = wq; d = (float4*)g_wq; o = i - HS4; }
    else if (i < HS4 + WQ4 + WK4)        { s = wk; d = (float4*)g_wk; o = i - HS4 - WQ4; }
    else if (i < HS4 + WQ4 + WK4 + WV4)  { s = wv; d = (float4*)g_wv; o = i - HS4 - WQ4 - WK4; }
    else                                 { s = wo; d = (float4*)g_wo; o = i - HS4 - WQ4 - WK4 - WV4; }
    float4 v = s[o];
    v.x = tf32r(v.x); v.y = tf32r(v.y); v.z = tf32r(v.z); v.w = tf32r(v.w);
    d[o] = v;
}

// ---------------------------------------------------------------------------
// TF32 GEMM, 3-stage cp.async pipeline. C[128,128] = A@B (+bias).
// 256 threads, 8 warps, warp tile 32x64, BK=32. Inputs pre-rounded to tf32.
// ---------------------------------------------------------------------------
#define G_LDA 36
#define G_LDB 136
#define G_AS_SZ (128 * G_LDA)
#define G_BS_SZ (32 * G_LDB)
#define G_STG (G_AS_SZ + G_BS_SZ)
#define G_SMEM_BYTES (3 * G_STG * 4)      // 107,520 B

__device__ __forceinline__ void gemm_tf32(
    const float* __restrict__ A, int lda,
    const float* __restrict__ B, int ldb,
    const float* __restrict__ bias,
    float* __restrict__ C, int ldc,
    int K, int m0, int n0, int round_out)
{
    extern __shared__ float smem[];
    const unsigned sbase = (unsigned)__cvta_generic_to_shared(smem);

    const int tid  = threadIdx.x;
    const int wid  = tid >> 5;
    const int lane = tid & 31;
    const int qt   = lane >> 2;
    const int qr   = lane & 3;
    const int wm   = (wid & 3) * 32;
    const int wn   = (wid >> 2) * 64;

    // per-thread load coordinates
    const int a_row = tid >> 3;           // 0..31 step base (4 iters of +32 rows)
    const int a_c4  = (tid & 7) * 4;
    const int b_row = tid >> 5;           // 0..7 (4 iters of +8 rows)
    const int b_c4  = (tid & 31) * 4;

    auto issue = [&](int s, int kk) {
#pragma unroll
        for (int f = 0; f < 4; f++) {
            int row = f * 32 + a_row;
            cp16(sbase + (unsigned)(s * G_STG + row * G_LDA + a_c4) * 4,
                 &A[(size_t)(m0 + row) * lda + kk + a_c4]);
        }
#pragma unroll
        for (int f = 0; f < 4; f++) {
            int row = f * 8 + b_row;
            cp16(sbase + (unsigned)(s * G_STG + G_AS_SZ + row * G_LDB + b_c4) * 4,
                 &B[(size_t)(kk + row) * ldb + n0 + b_c4]);
        }
        cp_commit();
    };

    float c[2][8][4];
#pragma unroll
    for (int mf = 0; mf < 2; mf++)
#pragma unroll
        for (int nf = 0; nf < 8; nf++)
#pragma unroll
            for (int e = 0; e < 4; e++) c[mf][nf][e] = 0.0f;

    const int niter = K >> 5;
    issue(0, 0);
    issue(1, 32);

    for (int i = 0; i < niter; i++) {
        cp_wait<1>();
        __syncthreads();
        const int s = i % 3;
        const float* As = smem + s * G_STG;
        const float* Bs = As + G_AS_SZ;

#pragma unroll
        for (int ks = 0; ks < 32; ks += 8) {
            unsigned a[2][4];
#pragma unroll
            for (int mf = 0; mf < 2; mf++) {
                int r = wm + mf * 16 + qt;
                a[mf][0] = __float_as_uint(As[r * G_LDA + ks + qr]);
                a[mf][1] = __float_as_uint(As[(r + 8) * G_LDA + ks + qr]);
                a[mf][2] = __float_as_uint(As[r * G_LDA + ks + qr + 4]);
                a[mf][3] = __float_as_uint(As[(r + 8) * G_LDA + ks + qr + 4]);
            }
#pragma unroll
            for (int nf = 0; nf < 8; nf++) {
                unsigned b0 = __float_as_uint(Bs[(ks + qr) * G_LDB + wn + nf * 8 + qt]);
                unsigned b1 = __float_as_uint(Bs[(ks + qr + 4) * G_LDB + wn + nf * 8 + qt]);
                mma8(c[0][nf], a[0][0], a[0][1], a[0][2], a[0][3], b0, b1);
                mma8(c[1][nf], a[1][0], a[1][1], a[1][2], a[1][3], b0, b1);
            }
        }

        int nk = i + 2;
        if (nk < niter) issue(nk % 3, nk * 32);
    }

    // Epilogue
#pragma unroll
    for (int nf = 0; nf < 8; nf++) {
        int col = n0 + wn + nf * 8 + 2 * qr;
        float b0 = bias ? bias[col]     : 0.0f;
        float b1 = bias ? bias[col + 1] : 0.0f;
#pragma unroll
        for (int mf = 0; mf < 2; mf++) {
            int r = m0 + wm + mf * 16 + qt;
            float2 v0, v1;
            v0.x = c[mf][nf][0] + b0; v0.y = c[mf][nf][1] + b1;
            v1.x = c[mf][nf][2] + b0; v1.y = c[mf][nf][3] + b1;
            if (round_out) {
                v0.x = tf32r(v0.x); v0.y = tf32r(v0.y);
                v1.x = tf32r(v1.x); v1.y = tf32r(v1.y);
            }
            *(float2*)&C[(size_t)r * ldc + col]       = v0;
            *(float2*)&C[(size_t)(r + 8) * ldc + col] = v1;
        }
    }
}

__global__ void __launch_bounds__(256, 2) qkv_gemm_kernel(
    const float* __restrict__ bq, const float* __restrict__ bk,
    const float* __restrict__ bv)
{
    int bx = blockIdx.x, by = blockIdx.y;
    const float* B; const float* bias; float* C; int ldn; int n0; int ro;
    if (bx < 16)      { B = g_wq; bias = bq; C = g_q; ldn = NH * HD;  n0 = bx * 128; ro = 0; }
    else if (bx < 18) { B = g_wk; bias = bk; C = g_k; ldn = NKV * HD; n0 = (bx - 16) * 128; ro = 0; }
    else              { B = g_wv; bias = bv; C = g_v; ldn = NKV * HD; n0 = (bx - 18) * 128; ro = 1; }
    gemm_tf32(g_hs, HID, B, ldn, bias, C, ldn, HID, by * 128, n0, ro);
}

__global__ void __launch_bounds__(256, 2) o_gemm_kernel(float* __restrict__ out)
{
    gemm_tf32(g_attn, NH * HD, g_wo, HID, nullptr, out, HID,
              NH * HD, blockIdx.y * 128, blockIdx.x * 128, 0);
}

// ---------------------------------------------------------------------------
// RoPE (in-place): rotate, scale q by SCALING, round to tf32.
// ---------------------------------------------------------------------------
__global__ void rope_kernel(const float* __restrict__ cosb,
                            const float* __restrict__ sinb)
{
    int idx = blockIdx.x * blockDim.x + threadIdx.x;
    const int QP = S_LEN * NH * 64;
    if (idx < QP) {
        int s = idx >> 10;
        int rest = idx & 1023;
        int h = rest >> 6;
        int d = rest & 63;
        float* p = g_q + (size_t)s * (NH * HD) + h * HD + d;
        float c  = cosb[s * HD + d];
        float sn = sinb[s * HD + d];
        float x0 = p[0], x1 = p[64];
        p[0]  = tf32r((x0 * c - x1 * sn) * SCALING);
        p[64] = tf32r((x1 * c + x0 * sn) * SCALING);
    } else {
        idx -= QP;
        int s = idx >> 7;
        int rest = idx & 127;
        int h = rest >> 6;
        int d = rest & 63;
        float* p = g_k + (size_t)s * (NKV * HD) + h * HD + d;
        float c  = cosb[s * HD + d];
        float sn = sinb[s * HD + d];
        float x0 = p[0], x1 = p[64];
        p[0]  = tf32r(x0 * c - x1 * sn);
        p[64] = tf32r(x1 * c + x0 * sn);
    }
}

// ---------------------------------------------------------------------------
// Flash attention, tf32 tensor cores. Inputs pre-rounded (q pre-scaled).
// BM=128, BN=64, D=128. 256 threads, 8 warps; warp owns 16 rows.
// ---------------------------------------------------------------------------
#define AT_LDQ 132
#define AT_LDK 132
#define AT_LDV 136
#define AT_LDP 68
#define AT_QS  0
#define AT_KS  (128 * AT_LDQ)
#define AT_VS  (AT_KS + 64 * AT_LDK)
#define AT_PS  (AT_VS + 64 * AT_LDV)
#define AT_FLOATS (AT_PS + 128 * AT_LDP)
#define AT_SMEM_BYTES (AT_FLOATS * 4)    // 171,008 B

__global__ void __launch_bounds__(256, 1) flash_attn_kernel()
{
    extern __shared__ float sm[];
    float* Qs = sm + AT_QS;
    float* Ks = sm + AT_KS;
    float* Vs = sm + AT_VS;
    float* Ps = sm + AT_PS;

    const int tid  = threadIdx.x;
    const int wid  = tid >> 5;
    const int lane = tid & 31;
    const int qt   = lane >> 2;
    const int qr   = lane & 3;
    const int head = blockIdx.y;
    const int kvh  = head >> 3;
    const int qb   = 15 - blockIdx.x;
    const int r0   = qb * 128;

    // Load Q tile (already tf32 + scaled)
#pragma unroll
    for (int f = 0; f < 16; f++) {
        int lin = f * 256 + tid;
        int row = lin >> 5;
        int c4  = (lin & 31) * 4;
        float4 v = *(const float4*)&g_q[(size_t)(r0 + row) * (NH * HD) + head * HD + c4];
        *(float4*)&Qs[row * AT_LDQ + c4] = v;
    }

    const int row_lo = wid * 16 + qt;
    const int row_hi = row_lo + 8;

    float o[16][4];
#pragma unroll
    for (int nf = 0; nf < 16; nf++)
#pragma unroll
        for (int e = 0; e < 4; e++) o[nf][e] = 0.0f;
    float m_lo = -1e30f, m_hi = -1e30f, l_lo = 0.0f, l_hi = 0.0f;

    const int ntiles = 2 * qb + 2;
    for (int t = 0; t < ntiles; t++) {
        const int k0 = t * 64;
        __syncthreads();

#pragma unroll
        for (int f = 0; f < 8; f++) {
            int lin = f * 256 + tid;
            int cc = lin >> 5;
            int d4 = (lin & 31) * 4;
            float4 kv = *(const float4*)&g_k[(size_t)(k0 + cc) * (NKV * HD) + kvh * HD + d4];
            *(float4*)&Ks[cc * AT_LDK + d4] = kv;
            float4 vv = *(const float4*)&g_v[(size_t)(k0 + cc) * (NKV * HD) + kvh * HD + d4];
            *(float4*)&Vs[cc * AT_LDV + d4] = vv;
        }
        __syncthreads();

        // ---- S = Q @ K^T ----
        float s[8][4];
#pragma unroll
        for (int nf = 0; nf < 8; nf++)
#pragma unroll
            for (int e = 0; e < 4; e++) s[nf][e] = 0.0f;

#pragma unroll
        for (int ks = 0; ks < 128; ks += 8) {
            unsigned a0 = __float_as_uint(Qs[row_lo * AT_LDQ + ks + qr]);
            unsigned a1 = __float_as_uint(Qs[row_hi * AT_LDQ + ks + qr]);
            unsigned a2 = __float_as_uint(Qs[row_lo * AT_LDQ + ks + qr + 4]);
            unsigned a3 = __float_as_uint(Qs[row_hi * AT_LDQ + ks + qr + 4]);
#pragma unroll
            for (int nf = 0; nf < 8; nf++) {
                unsigned b0 = __float_as_uint(Ks[(nf * 8 + qt) * AT_LDK + ks + qr]);
                unsigned b1 = __float_as_uint(Ks[(nf * 8 + qt) * AT_LDK + ks + qr + 4]);
                mma8(s[nf], a0, a1, a2, a3, b0, b1);
            }
        }

        // ---- causal mask + online softmax ----
        const bool need_mask = (t >= ntiles - 2);
        float mx_lo = -1e30f, mx_hi = -1e30f;
#pragma unroll
        for (int nf = 0; nf < 8; nf++) {
            if (need_mask) {
                int cg = k0 + nf * 8 + 2 * qr;
                int rg_lo = r0 + row_lo, rg_hi = r0 + row_hi;
                if (cg     > rg_lo) s[nf][0] = -1e30f;
                if (cg + 1 > rg_lo) s[nf][1] = -1e30f;
                if (cg     > rg_hi) s[nf][2] = -1e30f;
                if (cg + 1 > rg_hi) s[nf][3] = -1e30f;
            }
            mx_lo = fmaxf(mx_lo, fmaxf(s[nf][0], s[nf][1]));
            mx_hi = fmaxf(mx_hi, fmaxf(s[nf][2], s[nf][3]));
        }
        mx_lo = fmaxf(mx_lo, __shfl_xor_sync(0xffffffffu, mx_lo, 1));
        mx_lo = fmaxf(mx_lo, __shfl_xor_sync(0xffffffffu, mx_lo, 2));
        mx_hi = fmaxf(mx_hi, __shfl_xor_sync(0xffffffffu, mx_hi, 1));
        mx_hi = fmaxf(mx_hi, __shfl_xor_sync(0xffffffffu, mx_hi, 2));

        float mn_lo = fmaxf(m_lo, mx_lo);
        float mn_hi = fmaxf(m_hi, mx_hi);
        float f_lo = __expf(m_lo - mn_lo);
        float f_hi = __expf(m_hi - mn_hi);
        float sum_lo = 0.0f, sum_hi = 0.0f;
#pragma unroll
        for (int nf = 0; nf < 8; nf++) {
            float p0 = __expf(s[nf][0] - mn_lo);
            float p1 = __expf(s[nf][1] - mn_lo);
            float p2 = __expf(s[nf][2] - mn_hi);
            float p3 = __expf(s[nf][3] - mn_hi);
            sum_lo += p0 + p1;
            sum_hi += p2 + p3;
            int col = nf * 8 + 2 * qr;
            Ps[row_lo * AT_LDP + col]     = tf32r(p0);
            Ps[row_lo * AT_LDP + col + 1] = tf32r(p1);
            Ps[row_hi * AT_LDP + col]     = tf32r(p2);
            Ps[row_hi * AT_LDP + col + 1] = tf32r(p3);
        }
        sum_lo += __shfl_xor_sync(0xffffffffu, sum_lo, 1);
        sum_lo += __shfl_xor_sync(0xffffffffu, sum_lo, 2);
        sum_hi += __shfl_xor_sync(0xffffffffu, sum_hi, 1);
        sum_hi += __shfl_xor_sync(0xffffffffu, sum_hi, 2);

        l_lo = l_lo * f_lo + sum_lo;
        l_hi = l_hi * f_hi + sum_hi;
        m_lo = mn_lo;
        m_hi = mn_hi;
#pragma unroll
        for (int nf = 0; nf < 16; nf++) {
            o[nf][0] *= f_lo; o[nf][1] *= f_lo;
            o[nf][2] *= f_hi; o[nf][3] *= f_hi;
        }
        __syncwarp();

        // ---- O += P @ V ----
#pragma unroll
        for (int ks = 0; ks < 64; ks += 8) {
            unsigned a0 = __float_as_uint(Ps[row_lo * AT_LDP + ks + qr]);
            unsigned a1 = __float_as_uint(Ps[row_hi * AT_LDP + ks + qr]);
            unsigned a2 = __float_as_uint(Ps[row_lo * AT_LDP + ks + qr + 4]);
            unsigned a3 = __float_as_uint(Ps[row_hi * AT_LDP + ks + qr + 4]);
#pragma unroll
            for (int nf = 0; nf < 16; nf++) {
                unsigned b0 = __float_as_uint(Vs[(ks + qr) * AT_LDV + nf * 8 + qt]);
                unsigned b1 = __float_as_uint(Vs[(ks + qr + 4) * AT_LDV + nf * 8 + qt]);
                mma8(o[nf], a0, a1, a2, a3, b0, b1);
            }
        }
        __syncwarp();
    }

    // Epilogue: normalize, round to tf32 (o_gemm consumes directly)
    float inv_lo = 1.0f / l_lo;
    float inv_hi = 1.0f / l_hi;
#pragma unroll
    for (int nf = 0; nf < 16; nf++) {
        int col = head * HD + nf * 8 + 2 * qr;
        float2 v0, v1;
        v0.x = tf32r(o[nf][0] * inv_lo); v0.y = tf32r(o[nf][1] * inv_lo);
        v1.x = tf32r(o[nf][2] * inv_hi); v1.y = tf32r(o[nf][3] * inv_hi);
        *(float2*)&g_attn[(size_t)(r0 + row_lo) * (NH * HD) + col] = v0;
        *(float2*)&g_attn[(size_t)(r0 + row_hi) * (NH * HD) + col] = v1;
    }
}

// ---------------------------------------------------------------------------
extern "C" void kernel_launch(void* const* d_in, const int* in_sizes, int n_in,
                              void* d_out, int out_size)
{
    const float* hs   = (const float*)d_in[0];
    const float* cosb = (const float*)d_in[1];
    const float* sinb = (const float*)d_in[2];
    // d_in[3] = attention_mask (pure causal; applied analytically)
    const float* Wq = (const float*)d_in[4];
    const float* bq = (const float*)d_in[5];
    const float* Wk = (const float*)d_in[6];
    const float* bk = (const float*)d_in[7];
    const float* Wv = (const float*)d_in[8];
    const float* bv = (const float*)d_in[9];
    const float* Wo = (const float*)d_in[10];
    float* out = (float*)d_out;

    cudaFuncSetAttribute(flash_attn_kernel,
                         cudaFuncAttributeMaxDynamicSharedMemorySize, AT_SMEM_BYTES);
    cudaFuncSetAttribute(qkv_gemm_kernel,
                         cudaFuncAttributeMaxDynamicSharedMemorySize, G_SMEM_BYTES);
    cudaFuncSetAttribute(o_gemm_kernel,
                         cudaFuncAttributeMaxDynamicSharedMemorySize, G_SMEM_BYTES);

    tf32_prepass_kernel<<<(TOT4 + 255) / 256, 256>>>(
        (const float4*)hs, (const float4*)Wq, (const float4*)Wk,
        (const float4*)Wv, (const float4*)Wo);
    qkv_gemm_kernel<<<dim3(20, 16), 256, G_SMEM_BYTES>>>(bq, bk, bv);
    rope_kernel<<<(S_LEN * NH * 64 + S_LEN * NKV * 64) / 256, 256>>>(cosb, sinb);
    flash_attn_kernel<<<dim3(16, 16), 256, AT_SMEM_BYTES>>>();
    o_gemm_kernel<<<dim3(16, 16), 256, G_SMEM_BYTES>>>(out);
}

// round 5
// speedup vs baseline: 5.2662x; 1.5941x over previous
#include <cuda_runtime.h>
#include <cuda_bf16.h>

// Problem constants
#define S_LEN 2048
#define HID   2048
#define NH    16
#define NKV   2
#define HD    128
#define SCALING 0.08838834764831845f

// Scratch (device globals: allocation-free rule)
__device__ float g_q[S_LEN * NH * HD];
__device__ float g_k[S_LEN * NKV * HD];
__device__ float g_v[S_LEN * NKV * HD];
__device__ float g_attn[S_LEN * NH * HD];
// tf32-prerounded copies of inputs
__device__ float g_hs[S_LEN * HID];
__device__ float g_wq[HID * NH * HD];
__device__ float g_wk[HID * NKV * HD];
__device__ float g_wv[HID * NKV * HD];
__device__ float g_wo[NH * HD * HID];

// ---------------------------------------------------------------------------
// TF32 + cp.async helpers
// ---------------------------------------------------------------------------
__device__ __forceinline__ float tf32r(float f) {
    unsigned u;
    asm("cvt.rna.tf32.f32 %0, %1;" : "=r"(u) : "f"(f));
    return __uint_as_float(u);
}

__device__ __forceinline__ void mma8(float* c,
    unsigned a0, unsigned a1, unsigned a2, unsigned a3,
    unsigned b0, unsigned b1)
{
    asm volatile(
        "mma.sync.aligned.m16n8k8.row.col.f32.tf32.tf32.f32 "
        "{%0,%1,%2,%3}, {%4,%5,%6,%7}, {%8,%9}, {%0,%1,%2,%3};\n"
        : "+f"(c[0]), "+f"(c[1]), "+f"(c[2]), "+f"(c[3])
        : "r"(a0), "r"(a1), "r"(a2), "r"(a3), "r"(b0), "r"(b1));
}

__device__ __forceinline__ void cp16(unsigned saddr, const void* gptr) {
    asm volatile("cp.async.cg.shared.global [%0], [%1], 16;\n"
                 :: "r"(saddr), "l"(gptr));
}
__device__ __forceinline__ void cp_commit() {
    asm volatile("cp.async.commit_group;\n");
}
template<int N>
__device__ __forceinline__ void cp_wait() {
    asm volatile("cp.async.wait_group %0;\n" :: "n"(N));
}

// ---------------------------------------------------------------------------
// Prepass: round hs + weights to tf32 once.
// ---------------------------------------------------------------------------
#define HS4  1048576
#define WQ4  1048576
#define WK4  131072
#define WV4  131072
#define WO4  1048576
#define TOT4 (HS4 + WQ4 + WK4 + WV4 + WO4)

__global__ void tf32_prepass_kernel(
    const float4* __restrict__ hs, const float4* __restrict__ wq,
    const float4* __restrict__ wk, const float4* __restrict__ wv,
    const float4* __restrict__ wo)
{
    int i = blockIdx.x * 256 + threadIdx.x;
    if (i >= TOT4) return;
    const float4* s; float4* d; int o;
    if (i < HS4)                         { s = hs; d = (float4*)g_hs; o = i; }
    else if (i < HS4 + WQ4)              { s = wq; d = (float4*)g_wq; o = i - HS4; }
    else if (i < HS4 + WQ4 + WK4)        { s = wk; d = (float4*)g_wk; o = i - HS4 - WQ4; }
    else if (i < HS4 + WQ4 + WK4 + WV4)  { s = wv; d = (float4*)g_wv; o = i - HS4 - WQ4 - WK4; }
    else                                 { s = wo; d = (float4*)g_wo; o = i - HS4 - WQ4 - WK4 - WV4; }
    float4 v = s[o];
    v.x = tf32r(v.x); v.y = tf32r(v.y); v.z = tf32r(v.z); v.w = tf32r(v.w);
    d[o] = v;
}

// ---------------------------------------------------------------------------
// TF32 GEMM, 3-stage cp.async pipeline (unchanged from R4).
// ---------------------------------------------------------------------------
#define G_LDA 36
#define G_LDB 136
#define G_AS_SZ (128 * G_LDA)
#define G_BS_SZ (32 * G_LDB)
#define G_STG (G_AS_SZ + G_BS_SZ)
#define G_SMEM_BYTES (3 * G_STG * 4)

__device__ __forceinline__ void gemm_tf32(
    const float* __restrict__ A, int lda,
    const float* __restrict__ B, int ldb,
    const float* __restrict__ bias,
    float* __restrict__ C, int ldc,
    int K, int m0, int n0, int round_out)
{
    extern __shared__ float smem[];
    const unsigned sbase = (unsigned)__cvta_generic_to_shared(smem);

    const int tid  = threadIdx.x;
    const int wid  = tid >> 5;
    const int lane = tid & 31;
    const int qt   = lane >> 2;
    const int qr   = lane & 3;
    const int wm   = (wid & 3) * 32;
    const int wn   = (wid >> 2) * 64;

    const int a_row = tid >> 3;
    const int a_c4  = (tid & 7) * 4;
    const int b_row = tid >> 5;
    const int b_c4  = (tid & 31) * 4;

    auto issue = [&](int s, int kk) {
#pragma unroll
        for (int f = 0; f < 4; f++) {
            int row = f * 32 + a_row;
            cp16(sbase + (unsigned)(s * G_STG + row * G_LDA + a_c4) * 4,
                 &A[(size_t)(m0 + row) * lda + kk + a_c4]);
        }
#pragma unroll
        for (int f = 0; f < 4; f++) {
            int row = f * 8 + b_row;
            cp16(sbase + (unsigned)(s * G_STG + G_AS_SZ + row * G_LDB + b_c4) * 4,
                 &B[(size_t)(kk + row) * ldb + n0 + b_c4]);
        }
        cp_commit();
    };

    float c[2][8][4];
#pragma unroll
    for (int mf = 0; mf < 2; mf++)
#pragma unroll
        for (int nf = 0; nf < 8; nf++)
#pragma unroll
            for (int e = 0; e < 4; e++) c[mf][nf][e] = 0.0f;

    const int niter = K >> 5;
    issue(0, 0);
    issue(1, 32);

    for (int i = 0; i < niter; i++) {
        cp_wait<1>();
        __syncthreads();
        const int s = i % 3;
        const float* As = smem + s * G_STG;
        const float* Bs = As + G_AS_SZ;

#pragma unroll
        for (int ks = 0; ks < 32; ks += 8) {
            unsigned a[2][4];
#pragma unroll
            for (int mf = 0; mf < 2; mf++) {
                int r = wm + mf * 16 + qt;
                a[mf][0] = __float_as_uint(As[r * G_LDA + ks + qr]);
                a[mf][1] = __float_as_uint(As[(r + 8) * G_LDA + ks + qr]);
                a[mf][2] = __float_as_uint(As[r * G_LDA + ks + qr + 4]);
                a[mf][3] = __float_as_uint(As[(r + 8) * G_LDA + ks + qr + 4]);
            }
#pragma unroll
            for (int nf = 0; nf < 8; nf++) {
                unsigned b0 = __float_as_uint(Bs[(ks + qr) * G_LDB + wn + nf * 8 + qt]);
                unsigned b1 = __float_as_uint(Bs[(ks + qr + 4) * G_LDB + wn + nf * 8 + qt]);
                mma8(c[0][nf], a[0][0], a[0][1], a[0][2], a[0][3], b0, b1);
                mma8(c[1][nf], a[1][0], a[1][1], a[1][2], a[1][3], b0, b1);
            }
        }

        int nk = i + 2;
        if (nk < niter) issue(nk % 3, nk * 32);
    }

#pragma unroll
    for (int nf = 0; nf < 8; nf++) {
        int col = n0 + wn + nf * 8 + 2 * qr;
        float b0 = bias ? bias[col]     : 0.0f;
        float b1 = bias ? bias[col + 1] : 0.0f;
#pragma unroll
        for (int mf = 0; mf < 2; mf++) {
            int r = m0 + wm + mf * 16 + qt;
            float2 v0, v1;
            v0.x = c[mf][nf][0] + b0; v0.y = c[mf][nf][1] + b1;
            v1.x = c[mf][nf][2] + b0; v1.y = c[mf][nf][3] + b1;
            if (round_out) {
                v0.x = tf32r(v0.x); v0.y = tf32r(v0.y);
                v1.x = tf32r(v1.x); v1.y = tf32r(v1.y);
            }
            *(float2*)&C[(size_t)r * ldc + col]       = v0;
            *(float2*)&C[(size_t)(r + 8) * ldc + col] = v1;
        }
    }
}

__global__ void __launch_bounds__(256, 2) qkv_gemm_kernel(
    const float* __restrict__ bq, const float* __restrict__ bk,
    const float* __restrict__ bv)
{
    int bx = blockIdx.x, by = blockIdx.y;
    const float* B; const float* bias; float* C; int ldn; int n0; int ro;
    if (bx < 16)      { B = g_wq; bias = bq; C = g_q; ldn = NH * HD;  n0 = bx * 128; ro = 0; }
    else if (bx < 18) { B = g_wk; bias = bk; C = g_k; ldn = NKV * HD; n0 = (bx - 16) * 128; ro = 0; }
    else              { B = g_wv; bias = bv; C = g_v; ldn = NKV * HD; n0 = (bx - 18) * 128; ro = 1; }
    gemm_tf32(g_hs, HID, B, ldn, bias, C, ldn, HID, by * 128, n0, ro);
}

__global__ void __launch_bounds__(256, 2) o_gemm_kernel(float* __restrict__ out)
{
    gemm_tf32(g_attn, NH * HD, g_wo, HID, nullptr, out, HID,
              NH * HD, blockIdx.y * 128, blockIdx.x * 128, 0);
}

// ---------------------------------------------------------------------------
// RoPE (in-place): rotate, scale q by SCALING, round to tf32.
// ---------------------------------------------------------------------------
__global__ void rope_kernel(const float* __restrict__ cosb,
                            const float* __restrict__ sinb)
{
    int idx = blockIdx.x * blockDim.x + threadIdx.x;
    const int QP = S_LEN * NH * 64;
    if (idx < QP) {
        int s = idx >> 10;
        int rest = idx & 1023;
        int h = rest >> 6;
        int d = rest & 63;
        float* p = g_q + (size_t)s * (NH * HD) + h * HD + d;
        float c  = cosb[s * HD + d];
        float sn = sinb[s * HD + d];
        float x0 = p[0], x1 = p[64];
        p[0]  = tf32r((x0 * c - x1 * sn) * SCALING);
        p[64] = tf32r((x1 * c + x0 * sn) * SCALING);
    } else {
        idx -= QP;
        int s = idx >> 7;
        int rest = idx & 127;
        int h = rest >> 6;
        int d = rest & 63;
        float* p = g_k + (size_t)s * (NKV * HD) + h * HD + d;
        float c  = cosb[s * HD + d];
        float sn = sinb[s * HD + d];
        float x0 = p[0], x1 = p[64];
        p[0]  = tf32r(x0 * c - x1 * sn);
        p[64] = tf32r(x1 * c + x0 * sn);
    }
}

// ---------------------------------------------------------------------------
// Flash attention v2: tf32 MMA, cp.async double-buffered K/V, P in registers
// (shuffle redistribution), no P smem.
// BM=128, BN=64, D=128, 256 threads / 8 warps; warp owns 16 rows.
// ---------------------------------------------------------------------------
#define AT_LDQ 132
#define AT_LDK 132
#define AT_LDV 136
#define AT_KSTG (64 * AT_LDK)
#define AT_VSTG (64 * AT_LDV)
#define AT_QS  0
#define AT_K0  (128 * AT_LDQ)
#define AT_V0  (AT_K0 + 2 * AT_KSTG)
#define AT_FLOATS (AT_V0 + 2 * AT_VSTG)
#define AT_SMEM_BYTES (AT_FLOATS * 4)     // 204,800 B

__global__ void __launch_bounds__(256, 1) flash_attn_kernel()
{
    extern __shared__ float sm[];
    float* Qs = sm + AT_QS;
    const unsigned sbase = (unsigned)__cvta_generic_to_shared(sm);

    const int tid  = threadIdx.x;
    const int wid  = tid >> 5;
    const int lane = tid & 31;
    const int qt   = lane >> 2;
    const int qr   = lane & 3;
    const int head = blockIdx.y;
    const int kvh  = head >> 3;
    const int qb   = 15 - blockIdx.x;
    const int r0   = qb * 128;

    const int ld_c  = tid >> 5;           // 0..7 (row base, +8 per f)
    const int ld_d4 = (tid & 31) * 4;

    // Issue cp.async for K/V tile t into stage st
    auto issue = [&](int st, int t) {
        const int k0 = t * 64;
#pragma unroll
        for (int f = 0; f < 8; f++) {
            int cc = f * 8 + ld_c;
            const float* ksrc = &g_k[(size_t)(k0 + cc) * (NKV * HD) + kvh * HD + ld_d4];
            cp16(sbase + (unsigned)(AT_K0 + st * AT_KSTG + cc * AT_LDK + ld_d4) * 4, ksrc);
            const float* vsrc = &g_v[(size_t)(k0 + cc) * (NKV * HD) + kvh * HD + ld_d4];
            cp16(sbase + (unsigned)(AT_V0 + st * AT_VSTG + cc * AT_LDV + ld_d4) * 4, vsrc);
        }
        cp_commit();
    };

    const int ntiles = 2 * qb + 2;
    issue(0, 0);

    // Load Q tile (already tf32 + scaled) — overlaps with stage-0 cp.async
#pragma unroll
    for (int f = 0; f < 16; f++) {
        int lin = f * 256 + tid;
        int row = lin >> 5;
        int c4  = (lin & 31) * 4;
        float4 v = *(const float4*)&g_q[(size_t)(r0 + row) * (NH * HD) + head * HD + c4];
        *(float4*)&Qs[row * AT_LDQ + c4] = v;
    }

    const int row_lo = wid * 16 + qt;
    const int row_hi = row_lo + 8;

    float o[16][4];
#pragma unroll
    for (int nf = 0; nf < 16; nf++)
#pragma unroll
        for (int e = 0; e < 4; e++) o[nf][e] = 0.0f;
    float m_lo = -1e30f, m_hi = -1e30f, l_lo = 0.0f, l_hi = 0.0f;

    for (int t = 0; t < ntiles; t++) {
        const int k0 = t * 64;
        const int st = t & 1;
        if (t + 1 < ntiles) {
            issue(st ^ 1, t + 1);
            cp_wait<1>();
        } else {
            cp_wait<0>();
        }
        __syncthreads();   // stage st ready; prior readers of st^1 done

        const float* Ks = sm + AT_K0 + st * AT_KSTG;
        const float* Vs = sm + AT_V0 + st * AT_VSTG;

        // ---- S = Q @ K^T ----
        float s[8][4];
#pragma unroll
        for (int nf = 0; nf < 8; nf++)
#pragma unroll
            for (int e = 0; e < 4; e++) s[nf][e] = 0.0f;

#pragma unroll
        for (int ks = 0; ks < 128; ks += 8) {
            unsigned a0 = __float_as_uint(Qs[row_lo * AT_LDQ + ks + qr]);
            unsigned a1 = __float_as_uint(Qs[row_hi * AT_LDQ + ks + qr]);
            unsigned a2 = __float_as_uint(Qs[row_lo * AT_LDQ + ks + qr + 4]);
            unsigned a3 = __float_as_uint(Qs[row_hi * AT_LDQ + ks + qr + 4]);
#pragma unroll
            for (int nf = 0; nf < 8; nf++) {
                unsigned b0 = __float_as_uint(Ks[(nf * 8 + qt) * AT_LDK + ks + qr]);
                unsigned b1 = __float_as_uint(Ks[(nf * 8 + qt) * AT_LDK + ks + qr + 4]);
                mma8(s[nf], a0, a1, a2, a3, b0, b1);
            }
        }

        // ---- causal mask + online softmax (rows warp-local) ----
        const bool need_mask = (t >= ntiles - 2);
        float mx_lo = -1e30f, mx_hi = -1e30f;
#pragma unroll
        for (int nf = 0; nf < 8; nf++) {
            if (need_mask) {
                int cg = k0 + nf * 8 + 2 * qr;
                int rg_lo = r0 + row_lo, rg_hi = r0 + row_hi;
                if (cg     > rg_lo) s[nf][0] = -1e30f;
                if (cg + 1 > rg_lo) s[nf][1] = -1e30f;
                if (cg     > rg_hi) s[nf][2] = -1e30f;
                if (cg + 1 > rg_hi) s[nf][3] = -1e30f;
            }
            mx_lo = fmaxf(mx_lo, fmaxf(s[nf][0], s[nf][1]));
            mx_hi = fmaxf(mx_hi, fmaxf(s[nf][2], s[nf][3]));
        }
        mx_lo = fmaxf(mx_lo, __shfl_xor_sync(0xffffffffu, mx_lo, 1));
        mx_lo = fmaxf(mx_lo, __shfl_xor_sync(0xffffffffu, mx_lo, 2));
        mx_hi = fmaxf(mx_hi, __shfl_xor_sync(0xffffffffu, mx_hi, 1));
        mx_hi = fmaxf(mx_hi, __shfl_xor_sync(0xffffffffu, mx_hi, 2));

        float mn_lo = fmaxf(m_lo, mx_lo);
        float mn_hi = fmaxf(m_hi, mx_hi);
        float f_lo = __expf(m_lo - mn_lo);
        float f_hi = __expf(m_hi - mn_hi);
        float sum_lo = 0.0f, sum_hi = 0.0f;
#pragma unroll
        for (int nf = 0; nf < 8; nf++) {
            float p0 = __expf(s[nf][0] - mn_lo);
            float p1 = __expf(s[nf][1] - mn_lo);
            float p2 = __expf(s[nf][2] - mn_hi);
            float p3 = __expf(s[nf][3] - mn_hi);
            sum_lo += p0 + p1;
            sum_hi += p2 + p3;
            s[nf][0] = tf32r(p0);
            s[nf][1] = tf32r(p1);
            s[nf][2] = tf32r(p2);
            s[nf][3] = tf32r(p3);
        }
        sum_lo += __shfl_xor_sync(0xffffffffu, sum_lo, 1);
        sum_lo += __shfl_xor_sync(0xffffffffu, sum_lo, 2);
        sum_hi += __shfl_xor_sync(0xffffffffu, sum_hi, 1);
        sum_hi += __shfl_xor_sync(0xffffffffu, sum_hi, 2);

        l_lo = l_lo * f_lo + sum_lo;
        l_hi = l_hi * f_hi + sum_hi;
        m_lo = mn_lo;
        m_hi = mn_hi;
#pragma unroll
        for (int nf = 0; nf < 16; nf++) {
            o[nf][0] *= f_lo; o[nf][1] *= f_lo;
            o[nf][2] *= f_hi; o[nf][3] *= f_hi;
        }

        // ---- O += P @ V : P A-frags via shuffle redistribution ----
        // Thread holds s[g][e]: P[rows qt|qt+8][cols g*8 + 2qr (+1)].
        // A-frag for k-group g needs P[qt|qt+8][g*8 + qr (and +4)].
        const int src_a = (lane & ~3) | (qr >> 1);   // qt*4 + (qr>>1)
        const int src_b = src_a + 2;
        const bool odd = qr & 1;
#pragma unroll
        for (int g = 0; g < 8; g++) {
            float x0 = __shfl_sync(0xffffffffu, s[g][0], src_a);
            float x1 = __shfl_sync(0xffffffffu, s[g][1], src_a);
            float y0 = __shfl_sync(0xffffffffu, s[g][2], src_a);
            float y1 = __shfl_sync(0xffffffffu, s[g][3], src_a);
            float z0 = __shfl_sync(0xffffffffu, s[g][0], src_b);
            float z1 = __shfl_sync(0xffffffffu, s[g][1], src_b);
            float w0 = __shfl_sync(0xffffffffu, s[g][2], src_b);
            float w1 = __shfl_sync(0xffffffffu, s[g][3], src_b);
            unsigned a0 = __float_as_uint(odd ? x1 : x0);
            unsigned a1 = __float_as_uint(odd ? y1 : y0);
            unsigned a2 = __float_as_uint(odd ? z1 : z0);
            unsigned a3 = __float_as_uint(odd ? w1 : w0);
            const int ks = g * 8;
#pragma unroll
            for (int nf = 0; nf < 16; nf++) {
                unsigned b0 = __float_as_uint(Vs[(ks + qr) * AT_LDV + nf * 8 + qt]);
                unsigned b1 = __float_as_uint(Vs[(ks + qr + 4) * AT_LDV + nf * 8 + qt]);
                mma8(o[nf], a0, a1, a2, a3, b0, b1);
            }
        }
        __syncthreads();   // readers of stage st done before t+2 overwrites it
    }

    // Epilogue: normalize, round to tf32 (o_gemm consumes directly)
    float inv_lo = 1.0f / l_lo;
    float inv_hi = 1.0f / l_hi;
#pragma unroll
    for (int nf = 0; nf < 16; nf++) {
        int col = head * HD + nf * 8 + 2 * qr;
        float2 v0, v1;
        v0.x = tf32r(o[nf][0] * inv_lo); v0.y = tf32r(o[nf][1] * inv_lo);
        v1.x = tf32r(o[nf][2] * inv_hi); v1.y = tf32r(o[nf][3] * inv_hi);
        *(float2*)&g_attn[(size_t)(r0 + row_lo) * (NH * HD) + col] = v0;
        *(float2*)&g_attn[(size_t)(r0 + row_hi) * (NH * HD) + col] = v1;
    }
}

// ---------------------------------------------------------------------------
extern "C" void kernel_launch(void* const* d_in, const int* in_sizes, int n_in,
                              void* d_out, int out_size)
{
    const float* hs   = (const float*)d_in[0];
    const float* cosb = (const float*)d_in[1];
    const float* sinb = (const float*)d_in[2];
    // d_in[3] = attention_mask (pure causal; applied analytically)
    const float* Wq = (const float*)d_in[4];
    const float* bq = (const float*)d_in[5];
    const float* Wk = (const float*)d_in[6];
    const float* bk = (const float*)d_in[7];
    const float* Wv = (const float*)d_in[8];
    const float* bv = (const float*)d_in[9];
    const float* Wo = (const float*)d_in[10];
    float* out = (float*)d_out;

    cudaFuncSetAttribute(flash_attn_kernel,
                         cudaFuncAttributeMaxDynamicSharedMemorySize, AT_SMEM_BYTES);
    cudaFuncSetAttribute(qkv_gemm_kernel,
                         cudaFuncAttributeMaxDynamicSharedMemorySize, G_SMEM_BYTES);
    cudaFuncSetAttribute(o_gemm_kernel,
                         cudaFuncAttributeMaxDynamicSharedMemorySize, G_SMEM_BYTES);

    tf32_prepass_kernel<<<(TOT4 + 255) / 256, 256>>>(
        (const float4*)hs, (const float4*)Wq, (const float4*)Wk,
        (const float4*)Wv, (const float4*)Wo);
    qkv_gemm_kernel<<<dim3(20, 16), 256, G_SMEM_BYTES>>>(bq, bk, bv);
    rope_kernel<<<(S_LEN * NH * 64 + S_LEN * NKV * 64) / 256, 256>>>(cosb, sinb);
    flash_attn_kernel<<<dim3(16, 16), 256, AT_SMEM_BYTES>>>();
    o_gemm_kernel<<<dim3(16, 16), 256, G_SMEM_BYTES>>>(out);
}